// round 5
// baseline (speedup 1.0000x reference)
#include <cuda_runtime.h>

#define BATCH 2
#define NN 1024
#define CC 64
#define ROWS (BATCH * NN)   // 2048

// yhat = sqrt(2*log2e) * (X@W); R = 0.5*||yhat||^2
// t = <yhat_i,yhat_j> - R_i - R_j = -log2e * q;  adj = 2^t (ex2).
#define SCALE_Y 1.6983709f

__device__ float g_Yt[CC * ROWS];   // [d][row]
__device__ float g_R[ROWS];

// ---------------------------------------------------------------------------
// Kernel A: Y = scale * X @ W, transposed store + row norms.
// ---------------------------------------------------------------------------
__global__ void y_kernel(const float* __restrict__ X, const float* __restrict__ W) {
    __shared__ float Ws[64 * 64];
    __shared__ float Xs[8 * 64];
    __shared__ float Ys[64 * 9];
    const int tid = threadIdx.x;
    const int rowBase = blockIdx.x * 8;

    #pragma unroll
    for (int i = tid; i < 64 * 64; i += 128) Ws[i] = W[i];
    for (int i = tid; i < 8 * 64; i += 128) Xs[i] = X[rowBase * 64 + i];
    __syncthreads();

    const int warp = tid >> 5, lane = tid & 31;
    #pragma unroll
    for (int r2 = 0; r2 < 2; r2++) {
        const int row = warp * 2 + r2;
        float a0 = 0.f, a1 = 0.f;
        #pragma unroll
        for (int c0 = 0; c0 < 64; c0++) {
            const float xv = Xs[row * 64 + c0];
            a0 = fmaf(xv, Ws[c0 * 64 + lane],      a0);
            a1 = fmaf(xv, Ws[c0 * 64 + lane + 32], a1);
        }
        a0 *= SCALE_Y; a1 *= SCALE_Y;
        Ys[lane * 9 + row]        = a0;
        Ys[(lane + 32) * 9 + row] = a1;
        float s = a0 * a0 + a1 * a1;
        #pragma unroll
        for (int o = 16; o; o >>= 1) s += __shfl_xor_sync(0xffffffffu, s, o);
        if (lane == 0) g_R[rowBase + row] = 0.5f * s;
    }
    __syncthreads();
    for (int idx = tid; idx < 64 * 8; idx += 128) {
        const int d = idx >> 3, r = idx & 7;
        g_Yt[d * ROWS + rowBase + r] = Ys[d * 9 + r];
    }
}

// ---------------------------------------------------------------------------
__device__ __forceinline__ void fma32(float acc[8][4], float4 a0, float4 a1, float4 b) {
    const float av[8] = {a0.x, a0.y, a0.z, a0.w, a1.x, a1.y, a1.z, a1.w};
    const float bb[4] = {b.x, b.y, b.z, b.w};
    #pragma unroll
    for (int l = 0; l < 8; l++)
        #pragma unroll
        for (int k = 0; k < 4; k++)
            acc[l][k] = fmaf(av[l], bb[k], acc[l][k]);
}

// ---------------------------------------------------------------------------
// Kernel B: 128(i) x 64(j) tile, 256 threads, 8x4 per thread, software-
// pipelined smem->reg mainloop. Triangular grid: ti in [0,8) (128-row tiles),
// tj in [0, 2ti+2) (64-col tiles) => 72 tiles per batch, 144 blocks total.
// tj < 2ti: strictly sub-diagonal -> compute + mirror.
// tj in {2ti, 2ti+1}: straddles diagonal -> compute only (covers both sides).
// ---------------------------------------------------------------------------
__global__ void __launch_bounds__(256) adj_kernel(float* __restrict__ out) {
    extern __shared__ float sm[];
    float* Yi = sm;                    // [65][128] (d=64 row zero pad)
    float* Yj = sm + 65 * 128;         // [65][64]
    float* Ri = Yj + 65 * 64;          // [128]
    float* Rj = Ri + 128;              // [64]

    const int t = blockIdx.x, b = blockIdx.y;
    int ti = (int)((sqrtf(4.0f * (float)t + 1.0f) - 1.0f) * 0.5f);
    while ((ti + 1) * (ti + 2) <= t) ti++;
    while (ti * (ti + 1) > t) ti--;
    const int tj = t - ti * (ti + 1);

    const int tid = threadIdx.x;
    const int gi = b * NN + ti * 128;
    const int gj = b * NN + tj * 64;

    for (int idx = tid; idx < 65 * 128; idx += 256) {
        const int d = idx >> 7, r = idx & 127;
        Yi[idx] = (d < 64) ? g_Yt[d * ROWS + gi + r] : 0.0f;
    }
    for (int idx = tid; idx < 65 * 64; idx += 256) {
        const int d = idx >> 6, r = idx & 63;
        Yj[idx] = (d < 64) ? g_Yt[d * ROWS + gj + r] : 0.0f;
    }
    if (tid < 128)       Ri[tid]       = g_R[gi + tid];
    else if (tid < 192)  Rj[tid - 128] = g_R[gj + (tid - 128)];
    __syncthreads();

    const int tx = tid & 15;    // 16 groups x 4 cols = 64
    const int ty = tid >> 4;    // 16 groups x 8 rows = 128
    const int ai = ty * 8;
    const int bi = tx * 4;

    float acc[8][4];
    #pragma unroll
    for (int l = 0; l < 8; l++)
        #pragma unroll
        for (int k = 0; k < 4; k++) acc[l][k] = 0.f;

    // Software-pipelined mainloop: cur / nxt ping-pong, pad row kills guards.
    float4 ca0 = *(const float4*)&Yi[ai];
    float4 ca1 = *(const float4*)&Yi[ai + 4];
    float4 cb  = *(const float4*)&Yj[bi];
    #pragma unroll 2
    for (int d = 0; d < 64; d += 2) {
        const float4 na0 = *(const float4*)&Yi[(d + 1) * 128 + ai];
        const float4 na1 = *(const float4*)&Yi[(d + 1) * 128 + ai + 4];
        const float4 nb  = *(const float4*)&Yj[(d + 1) * 64 + bi];
        fma32(acc, ca0, ca1, cb);
        ca0 = *(const float4*)&Yi[(d + 2) * 128 + ai];   // d=62 -> pad row (zeros)
        ca1 = *(const float4*)&Yi[(d + 2) * 128 + ai + 4];
        cb  = *(const float4*)&Yj[(d + 2) * 64 + bi];
        fma32(acc, na0, na1, nb);
    }

    float Rli[8], Rlj[4];
    #pragma unroll
    for (int l = 0; l < 8; l++) Rli[l] = Ri[ai + l];
    #pragma unroll
    for (int k = 0; k < 4; k++) Rlj[k] = Rj[bi + k];

    const int iBase = ti * 128 + ai;   // global row
    const int jBase = tj * 64 + bi;    // global col
    #pragma unroll
    for (int l = 0; l < 8; l++) {
        #pragma unroll
        for (int k = 0; k < 4; k++) {
            const float tt = (acc[l][k] - Rli[l]) - Rlj[k];
            float e;
            asm("ex2.approx.ftz.f32 %0, %1;" : "=f"(e) : "f"(tt));
            if ((iBase + l) == (jBase + k)) e += 1.0f;
            acc[l][k] = e;
        }
    }

    const size_t outBase = (size_t)b * (size_t)NN * (size_t)NN;

    // Primary write: coalesced float4 (16 tx groups cover 256B per row).
    #pragma unroll
    for (int l = 0; l < 8; l++) {
        *(float4*)&out[outBase + (size_t)(iBase + l) * NN + jBase] =
            make_float4(acc[l][0], acc[l][1], acc[l][2], acc[l][3]);
    }

    // Mirror only strictly sub-diagonal tiles (race-free coverage).
    if (tj < 2 * ti) {
        #pragma unroll
        for (int k = 0; k < 4; k++) {
            const size_t base = outBase + (size_t)(jBase + k) * NN + iBase;
            *(float4*)&out[base]     = make_float4(acc[0][k], acc[1][k], acc[2][k], acc[3][k]);
            *(float4*)&out[base + 4] = make_float4(acc[4][k], acc[5][k], acc[6][k], acc[7][k]);
        }
    }
}

// ---------------------------------------------------------------------------
extern "C" void kernel_launch(void* const* d_in, const int* in_sizes, int n_in,
                              void* d_out, int out_size) {
    const float* X = (const float*)d_in[0];   // (2,1024,64)
    const float* W = (const float*)d_in[1];   // (64,64)
    float* out = (float*)d_out;               // (2,1024,1024)

    const int smemBytes = (65 * 128 + 65 * 64 + 128 + 64) * (int)sizeof(float); // 50688
    static int smem_set = 0;
    if (!smem_set) {
        cudaFuncSetAttribute(adj_kernel, cudaFuncAttributeMaxDynamicSharedMemorySize, smemBytes);
        smem_set = 1;
    }

    y_kernel<<<256, 128>>>(X, W);
    adj_kernel<<<dim3(72, 2), 256, smemBytes>>>(out);
    (void)in_sizes; (void)n_in; (void)out_size;
}

// round 7
// speedup vs baseline: 1.4147x; 1.4147x over previous
#include <cuda_runtime.h>
#include <cuda_bf16.h>
#include <cstdint>

#define BATCH 2
#define NN 1024
#define ROWS (BATCH * NN)   // 2048
#define SCALE_Y 1.6983709f  // sqrt(2*log2e): t = <yh_i,yh_j> - R_i - R_j = -log2e*q

__device__ __nv_bfloat16 g_Yb[ROWS * 64];  // row-major, 128B rows
__device__ float g_R[ROWS];                // 0.5*||bf16(yh)||^2 (consistent with g_Yb)

__device__ __forceinline__ uint32_t smem_u32(const void* p) {
    uint32_t a;
    asm("{ .reg .u64 t; cvta.to.shared.u64 t, %1; cvt.u32.u64 %0, t; }" : "=r"(a) : "l"(p));
    return a;
}
__device__ __forceinline__ uint32_t swz128(uint32_t off) { return off ^ ((off >> 3) & 0x70); }

__device__ __forceinline__ void ldsm_x4(uint32_t r[4], uint32_t addr) {
    asm volatile("ldmatrix.sync.aligned.m8n8.x4.shared.b16 {%0,%1,%2,%3}, [%4];"
                 : "=r"(r[0]), "=r"(r[1]), "=r"(r[2]), "=r"(r[3]) : "r"(addr));
}
__device__ __forceinline__ void mma16816(float c[4], const uint32_t a[4],
                                         uint32_t b0, uint32_t b1) {
    asm volatile(
        "mma.sync.aligned.m16n8k16.row.col.f32.bf16.bf16.f32 "
        "{%0,%1,%2,%3}, {%4,%5,%6,%7}, {%8,%9}, {%0,%1,%2,%3};"
        : "+f"(c[0]), "+f"(c[1]), "+f"(c[2]), "+f"(c[3])
        : "r"(a[0]), "r"(a[1]), "r"(a[2]), "r"(a[3]), "r"(b0), "r"(b1));
}

// FFMA-only 2^t (round-to-nearest split + deg-6 poly), FTZ. Validated in R3/R4.
__device__ __forceinline__ float exp2_poly(float tt) {
    const float MAGIC = 12582912.0f;     // 2^23 + 2^22
    const int   MAGIC_I = 0x4B400000;
    float sh = tt + MAGIC;
    float rn = sh - MAGIC;
    float f  = tt - rn;
    int   n  = __float_as_int(sh) - MAGIC_I;
    float p = 1.5403530e-4f;
    p = fmaf(p, f, 1.3333558e-3f);
    p = fmaf(p, f, 9.6181291e-3f);
    p = fmaf(p, f, 5.5504109e-2f);
    p = fmaf(p, f, 2.4022651e-1f);
    p = fmaf(p, f, 6.9314718e-1f);
    p = fmaf(p, f, 1.0f);
    float sc = __int_as_float((n + 127) << 23);
    return (n < -126) ? 0.0f : p * sc;
}

// ---------------------------------------------------------------------------
// Kernel A: yh = SCALE_Y * X @ W, bf16-rounded; R = 0.5*||bf16(yh)||^2.
// ---------------------------------------------------------------------------
__global__ void __launch_bounds__(256) y_kernel(const float* __restrict__ X,
                                                const float* __restrict__ W) {
    __shared__ float Ws[64 * 64];
    __shared__ float Xs[32 * 64];
    const int tid = threadIdx.x;
    const int rowBase = blockIdx.x * 32;

    for (int i = tid; i < 4096; i += 256) Ws[i] = W[i];
    for (int i = tid; i < 2048; i += 256) Xs[i] = X[rowBase * 64 + i];
    __syncthreads();

    const int warp = tid >> 5, lane = tid & 31;
    #pragma unroll
    for (int r = 0; r < 4; r++) {
        const int row = warp * 4 + r;
        float a0 = 0.f, a1 = 0.f;
        #pragma unroll
        for (int c0 = 0; c0 < 64; c0++) {
            const float xv = Xs[row * 64 + c0];
            a0 = fmaf(xv, Ws[c0 * 64 + lane],      a0);
            a1 = fmaf(xv, Ws[c0 * 64 + lane + 32], a1);
        }
        a0 *= SCALE_Y; a1 *= SCALE_Y;
        const __nv_bfloat16 b0 = __float2bfloat16(a0);
        const __nv_bfloat16 b1 = __float2bfloat16(a1);
        const float f0 = __bfloat162float(b0), f1 = __bfloat162float(b1);
        g_Yb[(rowBase + row) * 64 + lane]      = b0;
        g_Yb[(rowBase + row) * 64 + lane + 32] = b1;
        float s = f0 * f0 + f1 * f1;
        #pragma unroll
        for (int o = 16; o; o >>= 1) s += __shfl_xor_sync(0xffffffffu, s, o);
        if (lane == 0) g_R[rowBase + row] = 0.5f * s;
    }
}

// ---------------------------------------------------------------------------
// Kernel B: 128x128 tile via mma.sync bf16 (HMMA), poly-exp epilogue,
// direct register stores. grid (tj=8, ti=8, b=2), 256 threads (8 warps),
// warp w computes the 16-row strip [w*16, w*16+16) x 128 cols.
// ---------------------------------------------------------------------------
__global__ void __launch_bounds__(256) adj_kernel(float* __restrict__ out) {
    __shared__ __align__(1024) __nv_bfloat16 As[128 * 64];
    __shared__ __align__(1024) __nv_bfloat16 Bs[128 * 64];
    __shared__ float Rish[128], Rjsh[128];

    const int tid = threadIdx.x;
    const int wid = tid >> 5, lane = tid & 31;
    const int tj = blockIdx.x, ti = blockIdx.y, b = blockIdx.z;

    const int gi = b * NN + ti * 128;
    const int gj = b * NN + tj * 128;

    // Global -> swizzled smem (uint4 chunks; each bf16 row = 128B = 8 chunks)
    const uint4* srcA = (const uint4*)(g_Yb + (size_t)gi * 64);
    const uint4* srcB = (const uint4*)(g_Yb + (size_t)gj * 64);
    #pragma unroll
    for (int it = 0; it < 4; it++) {
        const int idx = tid + it * 256;
        const int row = idx >> 3, ch = idx & 7;
        const uint32_t sw = swz128(row * 128 + ch * 16);
        *(uint4*)((char*)As + sw) = srcA[idx];
        *(uint4*)((char*)Bs + sw) = srcB[idx];
    }
    if (tid < 128)  Rish[tid]       = g_R[gi + tid];
    else            Rjsh[tid - 128] = g_R[gj + (tid - 128)];
    __syncthreads();

    const uint32_t aBase = smem_u32(As), bBase = smem_u32(Bs);
    const int mrow0 = wid * 16;

    float acc[16][4];
    #pragma unroll
    for (int nb = 0; nb < 16; nb++)
        #pragma unroll
        for (int k = 0; k < 4; k++) acc[nb][k] = 0.f;

    #pragma unroll
    for (int ks = 0; ks < 4; ks++) {
        // A fragment (m16 x k16): matrices (m0-7,k0-7)(m8-15,k0-7)(m0-7,k8-15)(m8-15,k8-15)
        uint32_t a[4];
        {
            const int arow = mrow0 + ((lane >> 3) & 1) * 8 + (lane & 7);
            const int kb   = ks * 32 + (lane >> 4) * 16;
            ldsm_x4(a, aBase + swz128(arow * 128 + kb));
        }
        #pragma unroll
        for (int nb2 = 0; nb2 < 8; nb2++) {
            // B fragments for 2 n-blocks: (n0-7,k0-7)(n0-7,k8-15)(n8-15,k0-7)(n8-15,k8-15)
            uint32_t bf[4];
            const int nrow = nb2 * 16 + ((lane >> 4) & 1) * 8 + (lane & 7);
            const int kb   = ks * 32 + ((lane >> 3) & 1) * 16;
            ldsm_x4(bf, bBase + swz128(nrow * 128 + kb));
            mma16816(acc[nb2 * 2],     a, bf[0], bf[1]);
            mma16816(acc[nb2 * 2 + 1], a, bf[2], bf[3]);
        }
    }

    // Epilogue + store. Accum layout m16n8: c0,c1 @ (row=lane>>2, col=(lane&3)*2 +0/1),
    // c2,c3 @ row+8.
    const int rloc = lane >> 2;
    const float ri0 = Rish[mrow0 + rloc];
    const float ri1 = Rish[mrow0 + 8 + rloc];
    const bool diagTile = (ti == tj);
    const size_t outBase = (size_t)b * NN * NN;
    const int gRow0 = ti * 128 + mrow0 + rloc;
    const size_t o0 = outBase + (size_t)gRow0 * NN + tj * 128;
    const size_t o1 = o0 + 8u * NN;

    #pragma unroll
    for (int nb = 0; nb < 16; nb++) {
        const int col0 = nb * 8 + (lane & 3) * 2;
        const float rj0 = Rjsh[col0], rj1 = Rjsh[col0 + 1];
        float e00 = exp2_poly((acc[nb][0] - ri0) - rj0);
        float e01 = exp2_poly((acc[nb][1] - ri0) - rj1);
        float e10 = exp2_poly((acc[nb][2] - ri1) - rj0);
        float e11 = exp2_poly((acc[nb][3] - ri1) - rj1);
        if (diagTile) {
            const int lrow0 = mrow0 + rloc, lrow1 = lrow0 + 8;
            if (lrow0 == col0)     e00 = 2.0f;
            if (lrow0 == col0 + 1) e01 = 2.0f;
            if (lrow1 == col0)     e10 = 2.0f;
            if (lrow1 == col0 + 1) e11 = 2.0f;
        }
        *(float2*)&out[o0 + col0] = make_float2(e00, e01);
        *(float2*)&out[o1 + col0] = make_float2(e10, e11);
    }
}

// ---------------------------------------------------------------------------
extern "C" void kernel_launch(void* const* d_in, const int* in_sizes, int n_in,
                              void* d_out, int out_size) {
    const float* X = (const float*)d_in[0];   // (2,1024,64)
    const float* W = (const float*)d_in[1];   // (64,64)
    float* out = (float*)d_out;               // (2,1024,1024)

    y_kernel<<<64, 256>>>(X, W);
    adj_kernel<<<dim3(8, 8, 2), 256>>>(out);
    (void)in_sizes; (void)n_in; (void)out_size;
}

// round 8
// speedup vs baseline: 1.9552x; 1.3821x over previous
#include <cuda_runtime.h>
#include <cuda_bf16.h>
#include <cstdint>

#define BATCH 2
#define NN 1024
#define ROWS (BATCH * NN)   // 2048
#define SCALE_Y 1.6983709f  // sqrt(2*log2e): t = <yh_i,yh_j> - R_i - R_j = -log2e*q

__device__ __nv_bfloat16 g_Yb[ROWS * 64];  // row-major, 128B rows
__device__ float g_R[ROWS];                // 0.5*||bf16(yh)||^2

__device__ __forceinline__ uint32_t smem_u32(const void* p) {
    uint32_t a;
    asm("{ .reg .u64 t; cvta.to.shared.u64 t, %1; cvt.u32.u64 %0, t; }" : "=r"(a) : "l"(p));
    return a;
}
__device__ __forceinline__ uint32_t swz128(uint32_t off) { return off ^ ((off >> 3) & 0x70); }

__device__ __forceinline__ void ldsm_x4(uint32_t r[4], uint32_t addr) {
    asm volatile("ldmatrix.sync.aligned.m8n8.x4.shared.b16 {%0,%1,%2,%3}, [%4];"
                 : "=r"(r[0]), "=r"(r[1]), "=r"(r[2]), "=r"(r[3]) : "r"(addr));
}
__device__ __forceinline__ void mma16816(float c[4], const uint32_t a[4],
                                         uint32_t b0, uint32_t b1) {
    asm volatile(
        "mma.sync.aligned.m16n8k16.row.col.f32.bf16.bf16.f32 "
        "{%0,%1,%2,%3}, {%4,%5,%6,%7}, {%8,%9}, {%0,%1,%2,%3};"
        : "+f"(c[0]), "+f"(c[1]), "+f"(c[2]), "+f"(c[3])
        : "r"(a[0]), "r"(a[1]), "r"(a[2]), "r"(a[3]), "r"(b0), "r"(b1));
}

// FFMA-only 2^t, deg-4 (abs err ~4e-5 on [-0.5,0.5]); t <= 0 here, FTZ clamp.
__device__ __forceinline__ float exp2_poly(float tt) {
    const float MAGIC = 12582912.0f;     // 2^23 + 2^22
    const int   MAGIC_I = 0x4B400000;
    float sh = tt + MAGIC;
    float rn = sh - MAGIC;
    float f  = tt - rn;
    int   n  = __float_as_int(sh) - MAGIC_I;
    float p = 9.6181291e-3f;
    p = fmaf(p, f, 5.5504109e-2f);
    p = fmaf(p, f, 2.4022651e-1f);
    p = fmaf(p, f, 6.9314718e-1f);
    p = fmaf(p, f, 1.0f);
    float sc = __int_as_float((n + 127) << 23);
    return (n < -126) ? 0.0f : p * sc;
}

// ---------------------------------------------------------------------------
// Kernel A: yh = SCALE_Y * X @ W, bf16-rounded; R = 0.5*||bf16(yh)||^2.
// 128 blocks x 128 threads, 16 rows/block (4 rows per warp).
// ---------------------------------------------------------------------------
__global__ void __launch_bounds__(128) y_kernel(const float* __restrict__ X,
                                                const float* __restrict__ W) {
    __shared__ float Ws[64 * 64];
    __shared__ float Xs[16 * 64];
    const int tid = threadIdx.x;
    const int rowBase = blockIdx.x * 16;

    #pragma unroll
    for (int i = tid; i < 1024; i += 128)
        ((float4*)Ws)[i] = ((const float4*)W)[i];
    #pragma unroll
    for (int i = tid; i < 256; i += 128)
        ((float4*)Xs)[i] = ((const float4*)(X + rowBase * 64))[i];
    __syncthreads();

    const int warp = tid >> 5, lane = tid & 31;
    #pragma unroll
    for (int r = 0; r < 4; r++) {
        const int row = warp * 4 + r;
        float a0 = 0.f, a1 = 0.f;
        #pragma unroll
        for (int c0 = 0; c0 < 64; c0++) {
            const float xv = Xs[row * 64 + c0];
            a0 = fmaf(xv, Ws[c0 * 64 + lane],      a0);
            a1 = fmaf(xv, Ws[c0 * 64 + lane + 32], a1);
        }
        a0 *= SCALE_Y; a1 *= SCALE_Y;
        const __nv_bfloat16 b0 = __float2bfloat16(a0);
        const __nv_bfloat16 b1 = __float2bfloat16(a1);
        const float f0 = __bfloat162float(b0), f1 = __bfloat162float(b1);
        g_Yb[(rowBase + row) * 64 + lane]      = b0;
        g_Yb[(rowBase + row) * 64 + lane + 32] = b1;
        float s = f0 * f0 + f1 * f1;
        #pragma unroll
        for (int o = 16; o; o >>= 1) s += __shfl_xor_sync(0xffffffffu, s, o);
        if (lane == 0) g_R[rowBase + row] = 0.5f * s;
    }
}

// ---------------------------------------------------------------------------
// Kernel B: 128(i) x 64(j) tile via mma.sync bf16, poly-exp epilogue, direct
// register stores. grid (tj=16, ti=8, b=2) = 512... no: (16,8,2)=256 blocks,
// 256 threads (8 warps); warp w computes rows [w*16, w*16+16) x 64 cols.
// ---------------------------------------------------------------------------
__global__ void __launch_bounds__(256) adj_kernel(float* __restrict__ out) {
    __shared__ __align__(1024) __nv_bfloat16 As[128 * 64];
    __shared__ __align__(1024) __nv_bfloat16 Bs[64 * 64];
    __shared__ float Rish[128], Rjsh[64];

    const int tid = threadIdx.x;
    const int wid = tid >> 5, lane = tid & 31;
    const int tj = blockIdx.x, ti = blockIdx.y, b = blockIdx.z;

    const int gi = b * NN + ti * 128;
    const int gj = b * NN + tj * 64;

    const uint4* srcA = (const uint4*)(g_Yb + (size_t)gi * 64);
    const uint4* srcB = (const uint4*)(g_Yb + (size_t)gj * 64);
    #pragma unroll
    for (int it = 0; it < 4; it++) {
        const int idx = tid + it * 256;          // 1024 x 16B chunks (A)
        const int row = idx >> 3, ch = idx & 7;
        *(uint4*)((char*)As + swz128(row * 128 + ch * 16)) = srcA[idx];
    }
    #pragma unroll
    for (int it = 0; it < 2; it++) {
        const int idx = tid + it * 256;          // 512 x 16B chunks (B)
        const int row = idx >> 3, ch = idx & 7;
        *(uint4*)((char*)Bs + swz128(row * 128 + ch * 16)) = srcB[idx];
    }
    if (tid < 128)       Rish[tid]       = g_R[gi + tid];
    else if (tid < 192)  Rjsh[tid - 128] = g_R[gj + (tid - 128)];
    __syncthreads();

    const uint32_t aBase = smem_u32(As), bBase = smem_u32(Bs);
    const int mrow0 = wid * 16;

    float acc[8][4];
    #pragma unroll
    for (int nb = 0; nb < 8; nb++)
        #pragma unroll
        for (int k = 0; k < 4; k++) acc[nb][k] = 0.f;

    #pragma unroll
    for (int ks = 0; ks < 4; ks++) {
        uint32_t a[4];
        {
            const int arow = mrow0 + ((lane >> 3) & 1) * 8 + (lane & 7);
            const int kb   = ks * 32 + (lane >> 4) * 16;
            ldsm_x4(a, aBase + swz128(arow * 128 + kb));
        }
        #pragma unroll
        for (int nb2 = 0; nb2 < 4; nb2++) {
            uint32_t bf[4];
            const int nrow = nb2 * 16 + ((lane >> 4) & 1) * 8 + (lane & 7);
            const int kb   = ks * 32 + ((lane >> 3) & 1) * 16;
            ldsm_x4(bf, bBase + swz128(nrow * 128 + kb));
            mma16816(acc[nb2 * 2],     a, bf[0], bf[1]);
            mma16816(acc[nb2 * 2 + 1], a, bf[2], bf[3]);
        }
    }

    // Epilogue + store. Accum m16n8: c0,c1 @ (row=lane>>2, col=(lane&3)*2+{0,1}),
    // c2,c3 @ row+8.
    const int rloc = lane >> 2;
    const float ri0 = Rish[mrow0 + rloc];
    const float ri1 = Rish[mrow0 + 8 + rloc];
    const bool diagTile = (ti * 2 == tj || ti * 2 + 1 == tj);
    const int colOff = tj * 64;                   // global col base of tile
    const size_t outBase = (size_t)b * NN * NN;
    const int gRow0 = ti * 128 + mrow0 + rloc;
    const size_t o0 = outBase + (size_t)gRow0 * NN + colOff;
    const size_t o1 = o0 + 8u * NN;

    #pragma unroll
    for (int nb = 0; nb < 8; nb++) {
        const int col0 = nb * 8 + (lane & 3) * 2;
        const float rj0 = Rjsh[col0], rj1 = Rjsh[col0 + 1];
        float e00 = exp2_poly((acc[nb][0] - ri0) - rj0);
        float e01 = exp2_poly((acc[nb][1] - ri0) - rj1);
        float e10 = exp2_poly((acc[nb][2] - ri1) - rj0);
        float e11 = exp2_poly((acc[nb][3] - ri1) - rj1);
        if (diagTile) {
            const int lrow0 = ti * 128 + mrow0 + rloc;   // global row
            const int gcol0 = colOff + col0;
            if (lrow0 == gcol0)         e00 = 2.0f;
            if (lrow0 == gcol0 + 1)     e01 = 2.0f;
            if (lrow0 + 8 == gcol0)     e10 = 2.0f;
            if (lrow0 + 8 == gcol0 + 1) e11 = 2.0f;
        }
        *(float2*)&out[o0 + col0] = make_float2(e00, e01);
        *(float2*)&out[o1 + col0] = make_float2(e10, e11);
    }
}

// ---------------------------------------------------------------------------
extern "C" void kernel_launch(void* const* d_in, const int* in_sizes, int n_in,
                              void* d_out, int out_size) {
    const float* X = (const float*)d_in[0];   // (2,1024,64)
    const float* W = (const float*)d_in[1];   // (64,64)
    float* out = (float*)d_out;               // (2,1024,1024)

    y_kernel<<<128, 128>>>(X, W);
    adj_kernel<<<dim3(16, 8, 2), 256>>>(out);
    (void)in_sizes; (void)n_in; (void)out_size;
}